// round 1
// baseline (speedup 1.0000x reference)
#include <cuda_runtime.h>
#include <cuda_bf16.h>
#include <cstdint>

// ---------------------------------------------------------------------------
// MultiHeadRegionalAttention2D
//   x:[1,128,192,192]  wq,wk,wv:[256,128]  out:[1,256,192,192]
//
// Decomposition (see analysis): Q and K are shifted identically, so
//   g[head,p]  = (sum_{c in head} q[c,p]*k[c,p]) / 16
//   score_s(p) = softmax over 9 slots of g[head, p+delta_s]   (OOB logit = 0)
//   out[c,p]   = sum_s score_s * v[c, p+delta_s]              (OOB v = 0)
// ---------------------------------------------------------------------------

#define C_IN   128
#define D_OUT  256
#define HDIM   192
#define NPIX   (192*192)          // 36864
#define NHEAD  8

// scratch: qkv rows 0..255 = q, 256..511 = k, 512..767 = v
__device__ float d_qkv[768 * NPIX];
__device__ float d_g[NHEAD * NPIX];

typedef unsigned long long u64;

__device__ __forceinline__ u64 pk2(float a, float b) {
    u64 r; asm("mov.b64 %0,{%1,%2};" : "=l"(r) : "f"(a), "f"(b)); return r;
}
__device__ __forceinline__ u64 fma2(u64 a, u64 b, u64 c) {
    u64 d; asm("fma.rn.f32x2 %0,%1,%2,%3;" : "=l"(d) : "l"(a), "l"(b), "l"(c)); return d;
}
__device__ __forceinline__ float2 up2(u64 a) {
    float2 f; asm("mov.b64 {%0,%1},%2;" : "=f"(f.x), "=f"(f.y) : "l"(a)); return f;
}

// ---------------------------------------------------------------------------
// Kernel 1: qkv GEMM.  out[m][p] = sum_k w[m][k] * x[k][p]
// M=768 (grid.y=12 tiles of 64), P=36864 (grid.x=288 tiles of 128), K=128 (2 chunks of 64)
// 256 threads; thread = (warp w -> 8 output channels, lane -> 4 pixels).
// Packed f32x2 over pixel pairs -> 2x fp32 FMA throughput on sm_103a.
// ---------------------------------------------------------------------------
__global__ __launch_bounds__(256) void gemm_kernel(
    const float* __restrict__ x,
    const float* __restrict__ wq,
    const float* __restrict__ wk,
    const float* __restrict__ wv)
{
    __shared__ float xs[64 * 128];   // 32 KB: [k within chunk][pixel]
    __shared__ float ws[64 * 64];    // 16 KB: [k within chunk][m within tile]

    const int pBase = blockIdx.x * 128;
    const int mBase = blockIdx.y * 64;
    const float* wsrc = (mBase < 256) ? (wq + mBase * C_IN)
                      : (mBase < 512) ? (wk + (mBase - 256) * C_IN)
                                      : (wv + (mBase - 512) * C_IN);

    const int t    = threadIdx.x;
    const int lane = t & 31;
    const int w    = t >> 5;
    const int pOff = lane * 4;
    const int mOff = w * 8;

    u64 acc[8][2];
    #pragma unroll
    for (int c = 0; c < 8; c++) { acc[c][0] = 0ull; acc[c][1] = 0ull; }

    for (int kc = 0; kc < 2; kc++) {
        const int k0 = kc * 64;
        // load x chunk: 64 rows x 128 px (2048 float4 / 256 thr = 8 each)
        #pragma unroll
        for (int j = 0; j < 8; j++) {
            int idx = t + j * 256;
            int row = idx >> 5;
            int c4  = (idx & 31) << 2;
            *(float4*)(xs + row * 128 + c4) =
                *(const float4*)(x + (size_t)(k0 + row) * NPIX + pBase + c4);
        }
        // load w chunk transposed: ws[k][c] (4096 floats / 256 thr = 16 each)
        #pragma unroll
        for (int j = 0; j < 16; j++) {
            int idx = t + j * 256;
            int c = idx >> 6;
            int k = idx & 63;
            ws[k * 64 + c] = wsrc[c * C_IN + k0 + k];
        }
        __syncthreads();

        #pragma unroll 8
        for (int k = 0; k < 64; k++) {
            float4 xv = *(const float4*)(xs + k * 128 + pOff);
            u64 xlo = pk2(xv.x, xv.y);
            u64 xhi = pk2(xv.z, xv.w);
            #pragma unroll
            for (int c = 0; c < 8; c++) {
                float wv = ws[k * 64 + mOff + c];   // broadcast across lanes
                u64 w2 = pk2(wv, wv);
                acc[c][0] = fma2(w2, xlo, acc[c][0]);
                acc[c][1] = fma2(w2, xhi, acc[c][1]);
            }
        }
        __syncthreads();
    }

    #pragma unroll
    for (int c = 0; c < 8; c++) {
        float2 lo = up2(acc[c][0]);
        float2 hi = up2(acc[c][1]);
        *(float4*)(d_qkv + (size_t)(mBase + mOff + c) * NPIX + pBase + pOff) =
            make_float4(lo.x, lo.y, hi.x, hi.y);
    }
}

// ---------------------------------------------------------------------------
// Kernel 2: g[head][p] = (1/16) * sum_{c in head's 32 channels} q[c,p]*k[c,p]
// grid (36864/1024, 8) x 256 threads, 4 pixels per thread (float4).
// ---------------------------------------------------------------------------
__global__ __launch_bounds__(256) void g_kernel()
{
    const int p  = (blockIdx.x * blockDim.x + threadIdx.x) * 4;
    const int hd = blockIdx.y;

    const float* qp = d_qkv + (size_t)(hd * 32) * NPIX + p;
    const float* kp = d_qkv + (size_t)(256 + hd * 32) * NPIX + p;

    float a0 = 0.f, a1 = 0.f, a2 = 0.f, a3 = 0.f;
    #pragma unroll 8
    for (int c = 0; c < 32; c++) {
        float4 q = *(const float4*)(qp + (size_t)c * NPIX);
        float4 k = *(const float4*)(kp + (size_t)c * NPIX);
        a0 += q.x * k.x;
        a1 += q.y * k.y;
        a2 += q.z * k.z;
        a3 += q.w * k.w;
    }
    const float s = 1.0f / 16.0f;   // temper = int(sqrt(256))
    *(float4*)(d_g + (size_t)hd * NPIX + p) = make_float4(a0 * s, a1 * s, a2 * s, a3 * s);
}

// ---------------------------------------------------------------------------
// Kernel 3: softmax over 9 region slots + weighted gather of v.
// thread = (head, pixel quad).  OOB logits are exactly 0 (zero-padded qk),
// OOB v taps are 0.  Per 4 pixels: one softmax per head reused by 32 channels.
// grid (9216/128, 8) x 128 threads.
// ---------------------------------------------------------------------------
__global__ __launch_bounds__(128) void attn_kernel(float* __restrict__ out)
{
    const int t    = threadIdx.x;
    const int quad = blockIdx.x * blockDim.x + t;
    const int hd   = blockIdx.y;
    const int p4   = quad * 4;
    const int y    = p4 / HDIM;
    const int x4   = p4 - y * HDIM;

    bool rok[3];
    int  roff[3];
    const bool lok  = (x4 > 0);
    const bool rokc = (x4 + 4 < HDIM);

    // g window: rows y-1..y+1, cols x4-1..x4+4 (6 values per row)
    float win[3][6];
    #pragma unroll
    for (int r = 0; r < 3; r++) {
        int yy = y + r - 1;
        rok[r]  = ((unsigned)yy < (unsigned)HDIM);
        roff[r] = yy * HDIM + x4;
        if (rok[r]) {
            const float* gp = d_g + (size_t)hd * NPIX + roff[r];
            win[r][0] = lok ? gp[-1] : 0.f;
            float4 m4 = *(const float4*)gp;
            win[r][1] = m4.x; win[r][2] = m4.y; win[r][3] = m4.z; win[r][4] = m4.w;
            win[r][5] = rokc ? gp[4] : 0.f;
        } else {
            #pragma unroll
            for (int i = 0; i < 6; i++) win[r][i] = 0.f;
        }
    }

    // softmax per pixel (tap col for pixel px, slot (r,j) is window index px+j)
    float wt[9][4];
    #pragma unroll
    for (int px = 0; px < 4; px++) {
        float l[9];
        float m = -1e30f;
        #pragma unroll
        for (int r = 0; r < 3; r++)
            #pragma unroll
            for (int j = 0; j < 3; j++) {
                float v = win[r][px + j];
                l[r * 3 + j] = v;
                m = fmaxf(m, v);
            }
        float z = 0.f;
        #pragma unroll
        for (int s = 0; s < 9; s++) {
            float e = __expf(l[s] - m);
            wt[s][px] = e;
            z += e;
        }
        float inv = __fdividef(1.f, z);
        #pragma unroll
        for (int s = 0; s < 9; s++) wt[s][px] *= inv;
    }

    const float* vbase = d_qkv + (size_t)(512 + hd * 32) * NPIX;
    float* obase       = out   + (size_t)(hd * 32) * NPIX;

    for (int c = 0; c < 32; c++) {
        const float* vr = vbase + (size_t)c * NPIX;
        float a0 = 0.f, a1 = 0.f, a2 = 0.f, a3 = 0.f;
        #pragma unroll
        for (int r = 0; r < 3; r++) {
            float vw[6];
            if (rok[r]) {
                const float* vp = vr + roff[r];
                vw[0] = lok ? vp[-1] : 0.f;
                float4 m4 = *(const float4*)vp;
                vw[1] = m4.x; vw[2] = m4.y; vw[3] = m4.z; vw[4] = m4.w;
                vw[5] = rokc ? vp[4] : 0.f;
            } else {
                #pragma unroll
                for (int i = 0; i < 6; i++) vw[i] = 0.f;
            }
            #pragma unroll
            for (int j = 0; j < 3; j++) {
                const int s = r * 3 + j;
                a0 += wt[s][0] * vw[0 + j];
                a1 += wt[s][1] * vw[1 + j];
                a2 += wt[s][2] * vw[2 + j];
                a3 += wt[s][3] * vw[3 + j];
            }
        }
        *(float4*)(obase + (size_t)c * NPIX + p4) = make_float4(a0, a1, a2, a3);
    }
}

// ---------------------------------------------------------------------------
extern "C" void kernel_launch(void* const* d_in, const int* in_sizes, int n_in,
                              void* d_out, int out_size)
{
    const float* x  = (const float*)d_in[0];
    const float* wq = (const float*)d_in[1];
    const float* wk = (const float*)d_in[2];
    const float* wv = (const float*)d_in[3];
    float* out = (float*)d_out;

    // 1) q,k,v projections: [768,128] @ [128,36864]
    gemm_kernel<<<dim3(NPIX / 128, 768 / 64), 256>>>(x, wq, wk, wv);
    // 2) per-head qk reduction -> g[8][36864]
    g_kernel<<<dim3(NPIX / (256 * 4), NHEAD), 256>>>();
    // 3) 3x3 softmax + weighted gather of v
    attn_kernel<<<dim3((NPIX / 4) / 128, NHEAD), 128>>>(out);
}

// round 2
// speedup vs baseline: 1.6665x; 1.6665x over previous
#include <cuda_runtime.h>
#include <cuda_bf16.h>
#include <cstdint>

// ---------------------------------------------------------------------------
// MultiHeadRegionalAttention2D
//   x:[1,128,192,192]  wq,wk,wv:[256,128]  out:[1,256,192,192]
//
//   g[head,p]  = (sum_{c in head} q[c,p]*k[c,p]) / 16
//   score_s(p) = softmax over 9 slots of g[head, p+delta_s]   (OOB logit = 0)
//   out[c,p]   = sum_s score_s * v[c, p+delta_s]              (OOB v = 0)
//
// R2 changes: w pre-transposed -> vector broadcast LDS; f32x2 packs channel
// pairs (w-pairs alias LDS.128 regs, no dup MOVs); qk->g fused into the
// projection kernel so q,k never hit DRAM.
// ---------------------------------------------------------------------------

#define C_IN   128
#define HDIM   192
#define NPIX   (192*192)          // 36864
#define NHEAD  8

__device__ float d_v [256 * NPIX];        // v projection only
__device__ float d_g [NHEAD * NPIX];
__device__ float d_wT[C_IN * 768];        // [k][m]: m 0..255=wq, 256..511=wk, 512..767=wv

typedef unsigned long long u64;

__device__ __forceinline__ u64 pk2(float a, float b) {
    u64 r; asm("mov.b64 %0,{%1,%2};" : "=l"(r) : "f"(a), "f"(b)); return r;
}
__device__ __forceinline__ u64 fma2(u64 a, u64 b, u64 c) {
    u64 d; asm("fma.rn.f32x2 %0,%1,%2,%3;" : "=l"(d) : "l"(a), "l"(b), "l"(c)); return d;
}
__device__ __forceinline__ float2 up2(u64 a) {
    float2 f; asm("mov.b64 {%0,%1},%2;" : "=f"(f.x), "=f"(f.y) : "l"(a)); return f;
}

// ---------------------------------------------------------------------------
// Kernel 0: transpose weights into d_wT[k][m]  (768*128 elems, trivial)
// ---------------------------------------------------------------------------
__global__ __launch_bounds__(256) void wtrans_kernel(
    const float* __restrict__ wq,
    const float* __restrict__ wk,
    const float* __restrict__ wv)
{
    int id = blockIdx.x * 256 + threadIdx.x;        // 0..98303
    int m = id >> 7;
    int k = id & 127;
    float val = (m < 256) ? wq[m * C_IN + k]
              : (m < 512) ? wk[(m - 256) * C_IN + k]
                          : wv[(m - 512) * C_IN + k];
    d_wT[k * 768 + m] = val;
}

// ---------------------------------------------------------------------------
// Kernel 1: fused projection.
//   blockIdx.y <  8 : head mode -> computes q,k for head y over 128 px,
//                     reduces to g[y][pTile] in-block. No DRAM q/k.
//   blockIdx.y >= 8 : v mode -> 64 v-channels ((y-8)*64..) over 128 px -> d_v.
// 256 threads: warp w -> 8 channels (mOff=w*8), lane -> 4 pixels.
// f32x2 accumulators pack channel pairs; acc[cp][px].
// ---------------------------------------------------------------------------
__global__ __launch_bounds__(256, 2) void proj_kernel(const float* __restrict__ x)
{
    __shared__ float xs[64 * 128];   // 32 KB  [k][px]   (reused for qk exchange)
    __shared__ float ws[64 * 64];    // 16 KB  [k][c]

    const int y     = blockIdx.y;
    const int pBase = blockIdx.x * 128;
    const int t     = threadIdx.x;
    const int lane  = t & 31;
    const int w     = t >> 5;
    const int pOff  = lane * 4;
    const int mOff  = w * 8;

    // weight column for the load phase (fixed per thread)
    const int cFix = t & 63;
    const int kFix = t >> 6;
    const int mcol = (y < 8)
        ? ((cFix < 32) ? y * 32 + cFix : 256 + y * 32 + (cFix - 32))
        : 512 + (y - 8) * 64 + cFix;

    u64 acc[4][4];
    #pragma unroll
    for (int cp = 0; cp < 4; cp++)
        #pragma unroll
        for (int px = 0; px < 4; px++) acc[cp][px] = 0ull;

    for (int kc = 0; kc < 2; kc++) {
        const int k0 = kc * 64;
        // x chunk: 64 rows x 128 px
        {
            const int row0 = t >> 5;
            const int c4   = (t & 31) << 2;
            #pragma unroll
            for (int j = 0; j < 8; j++) {
                int row = row0 + 8 * j;
                *(float4*)(xs + row * 128 + c4) =
                    *(const float4*)(x + (size_t)(k0 + row) * NPIX + pBase + c4);
            }
        }
        // w chunk from d_wT: ws[k][c], conflict-free stores, coalesced loads
        #pragma unroll
        for (int j = 0; j < 16; j++) {
            int k = kFix + 4 * j;
            ws[k * 64 + cFix] = d_wT[(size_t)(k0 + k) * 768 + mcol];
        }
        __syncthreads();

        #pragma unroll 4
        for (int k = 0; k < 64; k++) {
            float4 xv = *(const float4*)(xs + k * 128 + pOff);
            u64 xd[4];
            xd[0] = pk2(xv.x, xv.x);
            xd[1] = pk2(xv.y, xv.y);
            xd[2] = pk2(xv.z, xv.z);
            xd[3] = pk2(xv.w, xv.w);
            float4 wa = *(const float4*)(ws + k * 64 + mOff);
            float4 wb = *(const float4*)(ws + k * 64 + mOff + 4);
            u64 wp[4];
            wp[0] = pk2(wa.x, wa.y);   // aliases LDS.128 result regs
            wp[1] = pk2(wa.z, wa.w);
            wp[2] = pk2(wb.x, wb.y);
            wp[3] = pk2(wb.z, wb.w);
            #pragma unroll
            for (int cp = 0; cp < 4; cp++)
                #pragma unroll
                for (int px = 0; px < 4; px++)
                    acc[cp][px] = fma2(wp[cp], xd[px], acc[cp][px]);
        }
        __syncthreads();
    }

    if (y >= 8) {
        // ---- v epilogue: write 8 channels x 4 px ----
        const int cbase = (y - 8) * 64 + mOff;
        #pragma unroll
        for (int cp = 0; cp < 4; cp++) {
            float2 a0 = up2(acc[cp][0]);
            float2 a1 = up2(acc[cp][1]);
            float2 a2 = up2(acc[cp][2]);
            float2 a3 = up2(acc[cp][3]);
            *(float4*)(d_v + (size_t)(cbase + 2 * cp) * NPIX + pBase + pOff) =
                make_float4(a0.x, a1.x, a2.x, a3.x);
            *(float4*)(d_v + (size_t)(cbase + 2 * cp + 1) * NPIX + pBase + pOff) =
                make_float4(a0.y, a1.y, a2.y, a3.y);
        }
    } else {
        // ---- qk epilogue: reduce q*k over the head's 32 channels -> g ----
        float* qsh = xs;               // [32][128]
        float* ps  = xs + 32 * 128;    // [4][128]

        if (w < 4) {   // q warps: local q channels w*8 .. w*8+7
            #pragma unroll
            for (int cp = 0; cp < 4; cp++) {
                float2 a0 = up2(acc[cp][0]);
                float2 a1 = up2(acc[cp][1]);
                float2 a2 = up2(acc[cp][2]);
                float2 a3 = up2(acc[cp][3]);
                int ch = mOff + 2 * cp;
                *(float4*)(qsh + ch * 128 + pOff) =
                    make_float4(a0.x, a1.x, a2.x, a3.x);
                *(float4*)(qsh + (ch + 1) * 128 + pOff) =
                    make_float4(a0.y, a1.y, a2.y, a3.y);
            }
        }
        __syncthreads();
        if (w >= 4) {  // k warps: dot with q over their 8 channels
            float s0 = 0.f, s1 = 0.f, s2 = 0.f, s3 = 0.f;
            #pragma unroll
            for (int cp = 0; cp < 4; cp++) {
                int ch = (w - 4) * 8 + 2 * cp;
                float4 q0 = *(const float4*)(qsh + ch * 128 + pOff);
                float4 q1 = *(const float4*)(qsh + (ch + 1) * 128 + pOff);
                float2 k0v = up2(acc[cp][0]);
                float2 k1v = up2(acc[cp][1]);
                float2 k2v = up2(acc[cp][2]);
                float2 k3v = up2(acc[cp][3]);
                s0 += k0v.x * q0.x + k0v.y * q1.x;
                s1 += k1v.x * q0.y + k1v.y * q1.y;
                s2 += k2v.x * q0.z + k2v.y * q1.z;
                s3 += k3v.x * q0.w + k3v.y * q1.w;
            }
            *(float4*)(ps + (w - 4) * 128 + pOff) = make_float4(s0, s1, s2, s3);
        }
        __syncthreads();
        if (t < 128) {
            float gv = (ps[t] + ps[128 + t] + ps[256 + t] + ps[384 + t]) * (1.0f / 16.0f);
            d_g[(size_t)y * NPIX + pBase + t] = gv;
        }
    }
}

// ---------------------------------------------------------------------------
// Kernel 2: softmax over 9 region slots + weighted gather of v.
// thread = (head, pixel quad). OOB logits exactly 0; OOB v taps 0.
// ---------------------------------------------------------------------------
__global__ __launch_bounds__(128) void attn_kernel(float* __restrict__ out)
{
    const int t    = threadIdx.x;
    const int quad = blockIdx.x * blockDim.x + t;
    const int hd   = blockIdx.y;
    const int p4   = quad * 4;
    const int yy0  = p4 / HDIM;
    const int x4   = p4 - yy0 * HDIM;

    bool rok[3];
    int  roff[3];
    const bool lok  = (x4 > 0);
    const bool rokc = (x4 + 4 < HDIM);

    float win[3][6];
    #pragma unroll
    for (int r = 0; r < 3; r++) {
        int yy = yy0 + r - 1;
        rok[r]  = ((unsigned)yy < (unsigned)HDIM);
        roff[r] = yy * HDIM + x4;
        if (rok[r]) {
            const float* gp = d_g + (size_t)hd * NPIX + roff[r];
            win[r][0] = lok ? gp[-1] : 0.f;
            float4 m4 = *(const float4*)gp;
            win[r][1] = m4.x; win[r][2] = m4.y; win[r][3] = m4.z; win[r][4] = m4.w;
            win[r][5] = rokc ? gp[4] : 0.f;
        } else {
            #pragma unroll
            for (int i = 0; i < 6; i++) win[r][i] = 0.f;
        }
    }

    float wt[9][4];
    #pragma unroll
    for (int px = 0; px < 4; px++) {
        float l[9];
        float m = -1e30f;
        #pragma unroll
        for (int r = 0; r < 3; r++)
            #pragma unroll
            for (int j = 0; j < 3; j++) {
                float v = win[r][px + j];
                l[r * 3 + j] = v;
                m = fmaxf(m, v);
            }
        float z = 0.f;
        #pragma unroll
        for (int s = 0; s < 9; s++) {
            float e = __expf(l[s] - m);
            wt[s][px] = e;
            z += e;
        }
        float inv = __fdividef(1.f, z);
        #pragma unroll
        for (int s = 0; s < 9; s++) wt[s][px] *= inv;
    }

    const float* vbase = d_v + (size_t)(hd * 32) * NPIX;
    float* obase       = out + (size_t)(hd * 32) * NPIX;

    for (int c = 0; c < 32; c++) {
        const float* vr = vbase + (size_t)c * NPIX;
        float a0 = 0.f, a1 = 0.f, a2 = 0.f, a3 = 0.f;
        #pragma unroll
        for (int r = 0; r < 3; r++) {
            float vw[6];
            if (rok[r]) {
                const float* vp = vr + roff[r];
                vw[0] = lok ? vp[-1] : 0.f;
                float4 m4 = *(const float4*)vp;
                vw[1] = m4.x; vw[2] = m4.y; vw[3] = m4.z; vw[4] = m4.w;
                vw[5] = rokc ? vp[4] : 0.f;
            } else {
                #pragma unroll
                for (int i = 0; i < 6; i++) vw[i] = 0.f;
            }
            #pragma unroll
            for (int j = 0; j < 3; j++) {
                const int s = r * 3 + j;
                a0 += wt[s][0] * vw[0 + j];
                a1 += wt[s][1] * vw[1 + j];
                a2 += wt[s][2] * vw[2 + j];
                a3 += wt[s][3] * vw[3 + j];
            }
        }
        *(float4*)(obase + (size_t)c * NPIX + p4) = make_float4(a0, a1, a2, a3);
    }
}

// ---------------------------------------------------------------------------
extern "C" void kernel_launch(void* const* d_in, const int* in_sizes, int n_in,
                              void* d_out, int out_size)
{
    const float* x  = (const float*)d_in[0];
    const float* wq = (const float*)d_in[1];
    const float* wk = (const float*)d_in[2];
    const float* wv = (const float*)d_in[3];
    float* out = (float*)d_out;

    wtrans_kernel<<<768 * C_IN / 256, 256>>>(wq, wk, wv);
    // y 0..7: per-head qk->g ; y 8..11: v channels
    proj_kernel<<<dim3(NPIX / 128, 12), 256>>>(x);
    attn_kernel<<<dim3((NPIX / 4) / 128, NHEAD), 128>>>(out);
}